// round 15
// baseline (speedup 1.0000x reference)
#include <cuda_runtime.h>
#include <cuda_fp16.h>
#include <cuda_bf16.h>

// Problem constants (B=1, L=1024, d_msa=256, d_pair=128, d_state=32, 36 RBF bins)
#define L 1024
#define DPAIR 128
#define DMSA 256
#define DSTATE 32
#define JT 256           // j-tile per block in pair kernel
#define TABN 2048        // distance-table entries
#define TABH 0.0125f     // table spacing in D
#define TABSCL 80.0f     // 1/TABH

#define MSA_OFF   0
#define PAIR_OFF  (L * DMSA)                         // 262144
#define STATE_OFF (PAIR_OFF + (size_t)L * L * DPAIR) // 134479872

// fixed-point scales for warp reductions of LN partials
#define S1SCL 32768.0f        // 2^15 for sum(x) partials
#define S1INV (1.0f / 32768.0f)
#define S2SCL 8192.0f         // 2^13 for sum(x^2) partials
#define S2INV (1.0f / 8192.0f)

// ---- device scratch (static: no allocation) ----
__device__ float g_left [L * DPAIR];   // left proj + b_proj + b_pair folded in
__device__ float g_right[L * DPAIR];
__device__ float g_cb   [L * 4];       // Cb xyz (padded)
__device__ float g_tabf [(TABN + 1) * DPAIR];   // pass-1 grid-point values
// g_tab[t*128+p] = half2( proj_p(t*h), proj_p((t+1)*h) )  -- 1 MB
__device__ __half2 g_tab[TABN * DPAIR];

struct alignas(16) h2x4 { __half2 a, b, c, d; };

// classic butterfly (for the small kernels)
__device__ __forceinline__ float warp_sum_shfl(float v) {
    #pragma unroll
    for (int o = 16; o; o >>= 1) v += __shfl_xor_sync(0xffffffffu, v, o);
    return v;
}

// ------------------------------------------------------------------
// Kernel T1: evaluate proj_p(D) at each grid point ONCE, 9-tap window.
// (excluded taps: |D-mu| > ~2.5 -> exp < 5e-10, invisible at 1e-3 tol)
// ------------------------------------------------------------------
__global__ __launch_bounds__(256) void table_pass1_kernel(const float* __restrict__ W) {
    int idx = blockIdx.x * blockDim.x + threadIdx.x;   // t*128 + p
    if (idx >= (TABN + 1) * DPAIR) return;
    int t = idx >> 7, p = idx & 127;
    float D = (float)t * TABH;
    int klo = min(max(__float2int_rn((D - 2.0f) * 1.75f) - 4, 0), 27);
    float s = 0.0f;
    #pragma unroll
    for (int m = 0; m < 9; m++) {
        int k = klo + m;
        float mu = 2.0f + (float)k * (20.0f / 35.0f);   // linspace(2,22,36)
        float a  = (D - mu) * 1.8f;                     // 1/sigma = 36/20
        s = fmaf(__expf(-a * a), W[p * 100 + k], s);
    }
    g_tabf[idx] = s;
}

// ------------------------------------------------------------------
// Kernel T2: pack (t, t+1) pairs into half2 for single-LDG lerp.
// ------------------------------------------------------------------
__global__ __launch_bounds__(256) void table_pass2_kernel() {
    int idx = blockIdx.x * blockDim.x + threadIdx.x;   // t*128 + p
    g_tab[idx] = __floats2half2_rn(g_tabf[idx], g_tabf[idx + DPAIR]);
}

// ------------------------------------------------------------------
// Kernel A: per-residue prep + fused msa layernorm.
// 128 blocks x (8 residues + 8 msa rows). W staged once per block.
// ------------------------------------------------------------------
#define PREP_RPB 8
__global__ __launch_bounds__(128) void prep_kernel(
    const float* __restrict__ state, const float* __restrict__ xyz,
    const float* __restrict__ W, const float* __restrict__ b_proj,
    const float* __restrict__ g_state, const float* __restrict__ b_state,
    const float* __restrict__ b_pair, float* __restrict__ out_state,
    const float* __restrict__ msa, const float* __restrict__ g_msa,
    const float* __restrict__ b_msa, float* __restrict__ out_msa)
{
    __shared__ float s_sn[DSTATE];
    __shared__ float sWl[128 * 65];   // W[:,36:100], padded stride
    int tid = threadIdx.x;
    int wid = tid >> 5, lane = tid & 31;

    for (int idx = tid; idx < 128 * 64; idx += 128) {
        int p = idx >> 6, k = idx & 63;
        sWl[p * 65 + k] = W[p * 100 + 36 + k];
    }

    float lb = b_proj[tid] + b_pair[tid];
    __syncthreads();

    for (int r = 0; r < PREP_RPB; r++) {
        int i = blockIdx.x * PREP_RPB + r;

        if (tid < 32) {
            float x = state[i * DSTATE + tid];
            float s1 = warp_sum_shfl(x);
            float s2 = warp_sum_shfl(x * x);
            float m   = s1 * (1.0f / 32.0f);
            float var = fmaf(-m, m, s2 * (1.0f / 32.0f));
            float sn  = (x - m) * rsqrtf(var + 1e-5f) * g_state[tid] + b_state[tid];
            s_sn[tid] = sn;
            out_state[i * DSTATE + tid] = sn;
        }
        __syncthreads();

        int p = tid;
        float l = lb;
        float rr = 0.0f;
        #pragma unroll
        for (int k = 0; k < 32; k++) {
            float s = s_sn[k];
            l  = fmaf(s, sWl[p * 65 + k],      l);
            rr = fmaf(s, sWl[p * 65 + 32 + k], rr);
        }
        g_left [i * DPAIR + p] = l;
        g_right[i * DPAIR + p] = rr;

        if (tid == 0) {
            const float* q = xyz + i * 9;
            float bx = q[3] - q[0], by = q[4] - q[1], bz = q[5] - q[2];
            float cx = q[6] - q[3], cy = q[7] - q[4], cz = q[8] - q[5];
            float ax = by * cz - bz * cy;
            float ay = bz * cx - bx * cz;
            float az = bx * cy - by * cx;
            g_cb[i * 4 + 0] = -0.58273431f * ax + 0.56802827f * bx - 0.54067466f * cx + q[3];
            g_cb[i * 4 + 1] = -0.58273431f * ay + 0.56802827f * by - 0.54067466f * cy + q[4];
            g_cb[i * 4 + 2] = -0.58273431f * az + 0.56802827f * bz - 0.54067466f * cz + q[5];
        }
        __syncthreads();   // protect s_sn before next residue
    }

    // ---- fused msa layernorm: 4 warps x 2 rows per block ----
    const float4* G4 = (const float4*)g_msa;
    const float4* B4 = (const float4*)b_msa;
    float4 G0 = G4[lane], G1 = G4[lane + 32];
    float4 B0 = B4[lane], B1 = B4[lane + 32];
    #pragma unroll
    for (int rr2 = 0; rr2 < 2; rr2++) {
        int r = blockIdx.x * PREP_RPB + rr2 * 4 + wid;
        const float4* row = (const float4*)(msa + (size_t)r * DMSA);
        float4 a0 = row[lane], a1 = row[lane + 32];
        float s1 = warp_sum_shfl(a0.x + a0.y + a0.z + a0.w + a1.x + a1.y + a1.z + a1.w);
        float s2 = warp_sum_shfl(a0.x * a0.x + a0.y * a0.y + a0.z * a0.z + a0.w * a0.w
                               + a1.x * a1.x + a1.y * a1.y + a1.z * a1.z + a1.w * a1.w);
        float m    = s1 * (1.0f / 256.0f);
        float var  = fmaf(-m, m, s2 * (1.0f / 256.0f));
        float rstd = rsqrtf(var + 1e-5f);
        float4 o0, o1;
        o0.x = fmaf((a0.x - m) * rstd, G0.x, B0.x);
        o0.y = fmaf((a0.y - m) * rstd, G0.y, B0.y);
        o0.z = fmaf((a0.z - m) * rstd, G0.z, B0.z);
        o0.w = fmaf((a0.w - m) * rstd, G0.w, B0.w);
        o1.x = fmaf((a1.x - m) * rstd, G1.x, B1.x);
        o1.y = fmaf((a1.y - m) * rstd, G1.y, B1.y);
        o1.z = fmaf((a1.z - m) * rstd, G1.z, B1.z);
        o1.w = fmaf((a1.w - m) * rstd, G1.w, B1.w);
        float4* orow = (float4*)(out_msa + (size_t)r * DMSA);
        orow[lane] = o0; orow[lane + 32] = o1;
    }
}

// ------------------------------------------------------------------
// Kernel C: main pair kernel. Block = (i, jtile); blockIdx.x = i
// fastest so consecutive blocks on an SM share the jtile (right-tile
// + table hot in L1/L2). Warp per pair-row, 4 channels/lane.
// Register diet for 5 CTAs/SM (40 warps): depth-3 prefetch kept on
// the DRAM pair stream; table + right read in-iteration (L2/L1 hits,
// latency absorbed by the extra occupancy).
// REDUX.SUM layernorm stats; half2 table lerp (1 LDG.128/pair).
// ------------------------------------------------------------------
__global__ __launch_bounds__(256, 5) void pair_kernel(
    const float* __restrict__ pair, const float* __restrict__ g_pair,
    float* __restrict__ out_pair)
{
    __shared__ float sU[JT];   // clamped table coordinate per j

    int i   = blockIdx.x;
    int jt0 = blockIdx.y * JT;
    int tid = threadIdx.x;

    // cooperative distance -> table coordinate (thread t handles j = jt0+t)
    {
        int j = jt0 + tid;
        float dx = g_cb[i * 4 + 0] - g_cb[j * 4 + 0];
        float dy = g_cb[i * 4 + 1] - g_cb[j * 4 + 1];
        float dz = g_cb[i * 4 + 2] - g_cb[j * 4 + 2];
        float d2 = dx * dx + dy * dy + dz * dz;
        float D  = sqrtf(fmaxf(d2, 1e-12f));
        sU[tid]  = fminf(D * TABSCL, 2046.999f);
    }
    __syncthreads();

    int w = tid >> 5, lane = tid & 31;
    int jb  = jt0 + w * 32;   // this warp's 32 consecutive j
    int jlb = w * 32;

    float4 Lf = *(const float4*)&g_left[i * DPAIR + lane * 4];  // incl biases
    float4 G  = ((const float4*)g_pair)[lane];

    const float4* pin  = (const float4*)pair    + ((size_t)i * L + jb) * (DPAIR / 4) + lane;
    float4*       pout = (float4*)out_pair      + ((size_t)i * L + jb) * (DPAIR / 4) + lane;
    const float4* rrow = (const float4*)&g_right[(size_t)jb * DPAIR] + lane;
    const __half2* tbase = g_tab + lane * 4;

    // ---- prologue: 3 pair rows in flight ----
    float4 P0 = __ldcs(pin);
    float4 P1 = __ldcs(pin + 32);
    float4 P2 = __ldcs(pin + 64);

    #pragma unroll 4
    for (int jj = 0; jj < 32; ++jj) {
        float4 c = P0;
        P0 = P1; P1 = P2;
        if (jj + 3 < 32) P2 = __ldcs(pin + (jj + 3) * 32);

        // table entry for this row (L2-resident 1MB table; hot rows in L1)
        float u  = sU[jlb + jj];
        int   t  = (int)u;
        float fc = u - (float)t;
        h2x4  Tc = *(const h2x4*)(tbase + t * DPAIR);
        // right row: L1/L2 resident (reused across i-blocks)
        float4 R = rrow[jj * 32];

        // layernorm stats over 128 channels: quantized partials + REDUX.SUM
        float p1 = c.x + c.y + c.z + c.w;
        float p2 = c.x * c.x + c.y * c.y + c.z * c.z + c.w * c.w;
        int i1 = __reduce_add_sync(0xffffffffu, __float2int_rn(p1 * S1SCL));
        int i2 = __reduce_add_sync(0xffffffffu, __float2int_rn(p2 * S2SCL));
        float s1 = (float)i1 * S1INV;
        float s2 = (float)i2 * S2INV;
        float m    = s1 * (1.0f / 128.0f);
        float var  = fmaf(-m, m, s2 * (1.0f / 128.0f));
        float rstd = rsqrtf(var + 1e-5f);

        // proj via table lerp + left + right
        float2 q0 = __half22float2(Tc.a);
        float2 q1 = __half22float2(Tc.b);
        float2 q2 = __half22float2(Tc.c);
        float2 q3 = __half22float2(Tc.d);
        float4 acc;
        acc.x = Lf.x + R.x + fmaf(fc, q0.y - q0.x, q0.x);
        acc.y = Lf.y + R.y + fmaf(fc, q1.y - q1.x, q1.x);
        acc.z = Lf.z + R.z + fmaf(fc, q2.y - q2.x, q2.x);
        acc.w = Lf.w + R.w + fmaf(fc, q3.y - q3.x, q3.x);

        float4 o;
        o.x = fmaf(c.x - m, rstd * G.x, acc.x);
        o.y = fmaf(c.y - m, rstd * G.y, acc.y);
        o.z = fmaf(c.z - m, rstd * G.z, acc.z);
        o.w = fmaf(c.w - m, rstd * G.w, acc.w);
        __stcs(pout + jj * 32, o);
    }
}

// ------------------------------------------------------------------
extern "C" void kernel_launch(void* const* d_in, const int* in_sizes, int n_in,
                              void* d_out, int out_size)
{
    // inputs: 0 seq, 1 msa, 2 pair, 3 xyz, 4 state, 5 W, 6 b_proj,
    //         7 g_state, 8 b_state, 9 g_pair, 10 b_pair, 11 g_msa, 12 b_msa
    const float* msa     = (const float*)d_in[1];
    const float* pair    = (const float*)d_in[2];
    const float* xyz     = (const float*)d_in[3];
    const float* state   = (const float*)d_in[4];
    const float* W       = (const float*)d_in[5];
    const float* b_proj  = (const float*)d_in[6];
    const float* g_state = (const float*)d_in[7];
    const float* b_state = (const float*)d_in[8];
    const float* g_pair  = (const float*)d_in[9];
    const float* b_pair  = (const float*)d_in[10];
    const float* g_msa   = (const float*)d_in[11];
    const float* b_msa   = (const float*)d_in[12];
    float* out = (float*)d_out;

    table_pass1_kernel<<<((TABN + 1) * DPAIR + 255) / 256, 256>>>(W);
    prep_kernel<<<L / PREP_RPB, 128>>>(state, xyz, W, b_proj, g_state, b_state,
                                       b_pair, out + STATE_OFF,
                                       msa, g_msa, b_msa, out + MSA_OFF);
    table_pass2_kernel<<<TABN * DPAIR / 256, 256>>>();
    pair_kernel<<<dim3(L, L / JT), 256>>>(pair, g_pair, out + PAIR_OFF);
}

// round 16
// speedup vs baseline: 1.0316x; 1.0316x over previous
#include <cuda_runtime.h>
#include <cuda_fp16.h>
#include <cuda_bf16.h>

// Problem constants (B=1, L=1024, d_msa=256, d_pair=128, d_state=32, 36 RBF bins)
#define L 1024
#define DPAIR 128
#define DMSA 256
#define DSTATE 32
#define JT 256           // j-tile per block in pair kernel
#define TABN 2048        // distance-table entries
#define TABH 0.0125f     // table spacing in D
#define TABSCL 80.0f     // 1/TABH

#define MSA_OFF   0
#define PAIR_OFF  (L * DMSA)                         // 262144
#define STATE_OFF (PAIR_OFF + (size_t)L * L * DPAIR) // 134479872

// fixed-point scales for warp reductions of LN partials
#define S1SCL 32768.0f        // 2^15 for sum(x) partials
#define S1INV (1.0f / 32768.0f)
#define S2SCL 8192.0f         // 2^13 for sum(x^2) partials
#define S2INV (1.0f / 8192.0f)

// ---- device scratch (static: no allocation) ----
__device__ float g_left [L * DPAIR];   // left proj + b_proj + b_pair folded in
__device__ float g_right[L * DPAIR];
__device__ float g_cb   [L * 4];       // Cb xyz (padded)
// g_tab[t*128+p] = half2( proj_p(t*h), proj_p((t+1)*h) )  -- 1 MB
__device__ __half2 g_tab[TABN * DPAIR];

struct alignas(16) h2x4 { __half2 a, b, c, d; };

// classic butterfly (for the small kernels)
__device__ __forceinline__ float warp_sum_shfl(float v) {
    #pragma unroll
    for (int o = 16; o; o >>= 1) v += __shfl_xor_sync(0xffffffffu, v, o);
    return v;
}

// ------------------------------------------------------------------
// Kernel A: fused setup, ONE launch.
//   blocks [0, TABN]           : table grid point t = blockIdx.x
//       thread p computes proj_p(t*h) with a 9-tap RBF window and
//       byte-stores the half value into entry t's .lo and entry
//       (t-1)'s .hi  (different bytes -> race-free, no second pass)
//   blocks [TABN+1, TABN+128]  : per-residue prep (8 residues each)
//       + fused msa layernorm (8 rows each)
// ------------------------------------------------------------------
#define PREP_RPB 8
#define PREP_BLOCKS (L / PREP_RPB)          // 128
#define SETUP_BLOCKS (TABN + 1 + PREP_BLOCKS)

__global__ __launch_bounds__(128) void setup_kernel(
    const float* __restrict__ state, const float* __restrict__ xyz,
    const float* __restrict__ W, const float* __restrict__ b_proj,
    const float* __restrict__ g_state, const float* __restrict__ b_state,
    const float* __restrict__ b_pair, float* __restrict__ out_state,
    const float* __restrict__ msa, const float* __restrict__ g_msa,
    const float* __restrict__ b_msa, float* __restrict__ out_msa)
{
    int tid = threadIdx.x;

    // ---------------- table role ----------------
    if (blockIdx.x <= TABN) {
        int t = blockIdx.x;          // grid point 0..2048
        int p = tid;                 // channel 0..127
        float D = (float)t * TABH;
        int klo = min(max(__float2int_rn((D - 2.0f) * 1.75f) - 4, 0), 27);
        float s = 0.0f;
        #pragma unroll
        for (int m = 0; m < 9; m++) {
            int k = klo + m;
            float mu = 2.0f + (float)k * (20.0f / 35.0f);   // linspace(2,22,36)
            float a  = (D - mu) * 1.8f;                     // 1/sigma = 36/20
            s = fmaf(__expf(-a * a), W[p * 100 + k], s);
        }
        __half h = __float2half_rn(s);
        __half* tab = (__half*)g_tab;
        if (t < TABN) tab[2 * (t * DPAIR + p)]           = h;  // entry t   .lo
        if (t >= 1)   tab[2 * ((t - 1) * DPAIR + p) + 1] = h;  // entry t-1 .hi
        return;
    }

    // ---------------- prep role ----------------
    __shared__ float s_sn[DSTATE];
    __shared__ float sWl[128 * 65];   // W[:,36:100], padded stride
    int blk = blockIdx.x - (TABN + 1);
    int wid = tid >> 5, lane = tid & 31;

    for (int idx = tid; idx < 128 * 64; idx += 128) {
        int p = idx >> 6, k = idx & 63;
        sWl[p * 65 + k] = W[p * 100 + 36 + k];
    }

    float lb = b_proj[tid] + b_pair[tid];
    __syncthreads();

    for (int r = 0; r < PREP_RPB; r++) {
        int i = blk * PREP_RPB + r;

        if (tid < 32) {
            float x = state[i * DSTATE + tid];
            float s1 = warp_sum_shfl(x);
            float s2 = warp_sum_shfl(x * x);
            float m   = s1 * (1.0f / 32.0f);
            float var = fmaf(-m, m, s2 * (1.0f / 32.0f));
            float sn  = (x - m) * rsqrtf(var + 1e-5f) * g_state[tid] + b_state[tid];
            s_sn[tid] = sn;
            out_state[i * DSTATE + tid] = sn;
        }
        __syncthreads();

        int p = tid;
        float l = lb;
        float rr = 0.0f;
        #pragma unroll
        for (int k = 0; k < 32; k++) {
            float s = s_sn[k];
            l  = fmaf(s, sWl[p * 65 + k],      l);
            rr = fmaf(s, sWl[p * 65 + 32 + k], rr);
        }
        g_left [i * DPAIR + p] = l;
        g_right[i * DPAIR + p] = rr;

        if (tid == 0) {
            const float* q = xyz + i * 9;
            float bx = q[3] - q[0], by = q[4] - q[1], bz = q[5] - q[2];
            float cx = q[6] - q[3], cy = q[7] - q[4], cz = q[8] - q[5];
            float ax = by * cz - bz * cy;
            float ay = bz * cx - bx * cz;
            float az = bx * cy - by * cx;
            g_cb[i * 4 + 0] = -0.58273431f * ax + 0.56802827f * bx - 0.54067466f * cx + q[3];
            g_cb[i * 4 + 1] = -0.58273431f * ay + 0.56802827f * by - 0.54067466f * cy + q[4];
            g_cb[i * 4 + 2] = -0.58273431f * az + 0.56802827f * bz - 0.54067466f * cz + q[5];
        }
        __syncthreads();   // protect s_sn before next residue
    }

    // ---- fused msa layernorm: 4 warps x 2 rows per block ----
    const float4* G4 = (const float4*)g_msa;
    const float4* B4 = (const float4*)b_msa;
    float4 G0 = G4[lane], G1 = G4[lane + 32];
    float4 B0 = B4[lane], B1 = B4[lane + 32];
    #pragma unroll
    for (int rr2 = 0; rr2 < 2; rr2++) {
        int r = blk * PREP_RPB + rr2 * 4 + wid;
        const float4* row = (const float4*)(msa + (size_t)r * DMSA);
        float4 a0 = row[lane], a1 = row[lane + 32];
        float s1 = warp_sum_shfl(a0.x + a0.y + a0.z + a0.w + a1.x + a1.y + a1.z + a1.w);
        float s2 = warp_sum_shfl(a0.x * a0.x + a0.y * a0.y + a0.z * a0.z + a0.w * a0.w
                               + a1.x * a1.x + a1.y * a1.y + a1.z * a1.z + a1.w * a1.w);
        float m    = s1 * (1.0f / 256.0f);
        float var  = fmaf(-m, m, s2 * (1.0f / 256.0f));
        float rstd = rsqrtf(var + 1e-5f);
        float4 o0, o1;
        o0.x = fmaf((a0.x - m) * rstd, G0.x, B0.x);
        o0.y = fmaf((a0.y - m) * rstd, G0.y, B0.y);
        o0.z = fmaf((a0.z - m) * rstd, G0.z, B0.z);
        o0.w = fmaf((a0.w - m) * rstd, G0.w, B0.w);
        o1.x = fmaf((a1.x - m) * rstd, G1.x, B1.x);
        o1.y = fmaf((a1.y - m) * rstd, G1.y, B1.y);
        o1.z = fmaf((a1.z - m) * rstd, G1.z, B1.z);
        o1.w = fmaf((a1.w - m) * rstd, G1.w, B1.w);
        float4* orow = (float4*)(out_msa + (size_t)r * DMSA);
        orow[lane] = o0; orow[lane + 32] = o1;
    }
}

// ------------------------------------------------------------------
// Kernel C: main pair kernel (R14 configuration — proven best).
// Block = (i, jtile); blockIdx.x = i fastest so consecutive blocks on
// an SM share the jtile (right-tile + table hot in L1/L2). Warp per
// pair-row, 4 channels/lane. Depth-3 prefetch on the DRAM pair
// stream, depth-2 on the table, right loaded in-iteration (cache hit).
// REDUX.SUM layernorm stats; half2 table lerp (1 LDG.128/pair).
// ------------------------------------------------------------------
__global__ __launch_bounds__(256, 4) void pair_kernel(
    const float* __restrict__ pair, const float* __restrict__ g_pair,
    float* __restrict__ out_pair)
{
    __shared__ float sU[JT];   // clamped table coordinate per j

    int i   = blockIdx.x;
    int jt0 = blockIdx.y * JT;
    int tid = threadIdx.x;

    // cooperative distance -> table coordinate (thread t handles j = jt0+t)
    {
        int j = jt0 + tid;
        float dx = g_cb[i * 4 + 0] - g_cb[j * 4 + 0];
        float dy = g_cb[i * 4 + 1] - g_cb[j * 4 + 1];
        float dz = g_cb[i * 4 + 2] - g_cb[j * 4 + 2];
        float d2 = dx * dx + dy * dy + dz * dz;
        float D  = sqrtf(fmaxf(d2, 1e-12f));
        sU[tid]  = fminf(D * TABSCL, 2046.999f);
    }
    __syncthreads();

    int w = tid >> 5, lane = tid & 31;
    int jb  = jt0 + w * 32;   // this warp's 32 consecutive j
    int jlb = w * 32;

    float4 Lf = *(const float4*)&g_left[i * DPAIR + lane * 4];  // incl biases
    float4 G  = ((const float4*)g_pair)[lane];

    const float4* pin  = (const float4*)pair    + ((size_t)i * L + jb) * (DPAIR / 4) + lane;
    float4*       pout = (float4*)out_pair      + ((size_t)i * L + jb) * (DPAIR / 4) + lane;
    const float4* rrow = (const float4*)&g_right[(size_t)jb * DPAIR] + lane;

    // ---- prologue: 3 pair rows + table row 0 in flight ----
    float4 P0 = __ldcs(pin);
    float4 P1 = __ldcs(pin + 32);
    float4 P2 = __ldcs(pin + 64);
    float u0 = sU[jlb];
    int   t0 = (int)u0;
    float fc = u0 - (float)t0;
    h2x4  Tc = *(const h2x4*)(g_tab + t0 * DPAIR + lane * 4);

    #pragma unroll 4
    for (int jj = 0; jj < 32; ++jj) {
        float4 c = P0;
        P0 = P1; P1 = P2;
        if (jj + 3 < 32) P2 = __ldcs(pin + (jj + 3) * 32);

        // next row's table entry (depth-2)
        float fn = fc; h2x4 Tn = Tc;
        if (jj + 1 < 32) {
            float u = sU[jlb + jj + 1];
            int   t = (int)u;
            fn = u - (float)t;
            Tn = *(const h2x4*)(g_tab + t * DPAIR + lane * 4);
        }
        // right row: issued early, L1/L2 resident (reused across i-blocks)
        float4 R = rrow[jj * 32];

        // layernorm stats over 128 channels: quantized partials + REDUX.SUM
        float p1 = c.x + c.y + c.z + c.w;
        float p2 = c.x * c.x + c.y * c.y + c.z * c.z + c.w * c.w;
        int i1 = __reduce_add_sync(0xffffffffu, __float2int_rn(p1 * S1SCL));
        int i2 = __reduce_add_sync(0xffffffffu, __float2int_rn(p2 * S2SCL));
        float s1 = (float)i1 * S1INV;
        float s2 = (float)i2 * S2INV;
        float m    = s1 * (1.0f / 128.0f);
        float var  = fmaf(-m, m, s2 * (1.0f / 128.0f));
        float rstd = rsqrtf(var + 1e-5f);

        // proj via table lerp + left + right
        float2 q0 = __half22float2(Tc.a);
        float2 q1 = __half22float2(Tc.b);
        float2 q2 = __half22float2(Tc.c);
        float2 q3 = __half22float2(Tc.d);
        float4 acc;
        acc.x = Lf.x + R.x + fmaf(fc, q0.y - q0.x, q0.x);
        acc.y = Lf.y + R.y + fmaf(fc, q1.y - q1.x, q1.x);
        acc.z = Lf.z + R.z + fmaf(fc, q2.y - q2.x, q2.x);
        acc.w = Lf.w + R.w + fmaf(fc, q3.y - q3.x, q3.x);

        float4 o;
        o.x = fmaf(c.x - m, rstd * G.x, acc.x);
        o.y = fmaf(c.y - m, rstd * G.y, acc.y);
        o.z = fmaf(c.z - m, rstd * G.z, acc.z);
        o.w = fmaf(c.w - m, rstd * G.w, acc.w);
        __stcs(pout + jj * 32, o);

        fc = fn; Tc = Tn;
    }
}

// ------------------------------------------------------------------
extern "C" void kernel_launch(void* const* d_in, const int* in_sizes, int n_in,
                              void* d_out, int out_size)
{
    // inputs: 0 seq, 1 msa, 2 pair, 3 xyz, 4 state, 5 W, 6 b_proj,
    //         7 g_state, 8 b_state, 9 g_pair, 10 b_pair, 11 g_msa, 12 b_msa
    const float* msa     = (const float*)d_in[1];
    const float* pair    = (const float*)d_in[2];
    const float* xyz     = (const float*)d_in[3];
    const float* state   = (const float*)d_in[4];
    const float* W       = (const float*)d_in[5];
    const float* b_proj  = (const float*)d_in[6];
    const float* g_state = (const float*)d_in[7];
    const float* b_state = (const float*)d_in[8];
    const float* g_pair  = (const float*)d_in[9];
    const float* b_pair  = (const float*)d_in[10];
    const float* g_msa   = (const float*)d_in[11];
    const float* b_msa   = (const float*)d_in[12];
    float* out = (float*)d_out;

    setup_kernel<<<SETUP_BLOCKS, 128>>>(state, xyz, W, b_proj, g_state, b_state,
                                        b_pair, out + STATE_OFF,
                                        msa, g_msa, b_msa, out + MSA_OFF);
    pair_kernel<<<dim3(L, L / JT), 256>>>(pair, g_pair, out + PAIR_OFF);
}